// round 10
// baseline (speedup 1.0000x reference)
#include <cuda_runtime.h>
#include <cuda_bf16.h>
#include <cstdint>

// ShiftDecoderNet: mma.sync bf16 split-precision, prepass-converted weights,
// cp.async double-buffered staging, 4M x 2N warp tiling. CTA=128 rows, grid=256.

#define NT 256
#define OFF_P   0        // params: 1600 floats
#define OFF_R   6400     // LN partial sums: float2[128][2]
#define OFF_X   8448     // X bf16 [128][144B]
#define OFF_A   26880    // a_bits bf16 [128][144B]
#define OFF_WB  45312    // 2 weight buffers x 24576B
#define OFF_PB  45312    // probs fp32 [64][129] overlays weight buffers
#define OFF_H   94464    // h hi/lo bf16 [128][1040B]
#define SMEM_TOTAL 227584
#define WBUF 24576

// preconverted weights: [k16 chunk][hi plane][lo plane], rows padded to 48B
__device__ __align__(16) unsigned char gW1d[4  * 24576];  // 256 rows, lo at +12288
__device__ __align__(16) unsigned char gW2d[16 * 24576];  // 256 rows, lo at +12288
__device__ __align__(16) unsigned char gW3d[16 * 6144];   // 64 rows,  lo at +3072

__device__ __forceinline__ uint32_t smem_u32(const void* p){
  uint32_t a; asm("{ .reg .u64 t; cvta.to.shared.u64 t, %1; cvt.u32.u64 %0, t; }":"=r"(a):"l"(p)); return a;
}
__device__ __forceinline__ void ldsm_x4(uint32_t* a, uint32_t addr){
  asm volatile("ldmatrix.sync.aligned.m8n8.x4.shared.b16 {%0,%1,%2,%3},[%4];"
    :"=r"(a[0]),"=r"(a[1]),"=r"(a[2]),"=r"(a[3]):"r"(addr));
}
__device__ __forceinline__ void ldsm_x2(uint32_t* b, uint32_t addr){
  asm volatile("ldmatrix.sync.aligned.m8n8.x2.shared.b16 {%0,%1},[%2];"
    :"=r"(b[0]),"=r"(b[1]):"r"(addr));
}
__device__ __forceinline__ void mma_bf16(float* d, const uint32_t* a, const uint32_t* b){
  asm volatile("mma.sync.aligned.m16n8k16.row.col.f32.bf16.bf16.f32 "
    "{%0,%1,%2,%3},{%4,%5,%6,%7},{%8,%9},{%0,%1,%2,%3};"
    :"+f"(d[0]),"+f"(d[1]),"+f"(d[2]),"+f"(d[3])
    :"r"(a[0]),"r"(a[1]),"r"(a[2]),"r"(a[3]),"r"(b[0]),"r"(b[1]));
}
__device__ __forceinline__ void split2(float x0,float x1,uint32_t&hi,uint32_t&lo){
  __nv_bfloat162 h=__floats2bfloat162_rn(x0,x1);
  float r0=x0-__bfloat162float(h.x), r1=x1-__bfloat162float(h.y);
  __nv_bfloat162 l2=__floats2bfloat162_rn(r0,r1);
  hi=*(uint32_t*)&h; lo=*(uint32_t*)&l2;
}
#define CP16(dst,src) asm volatile("cp.async.cg.shared.global [%0],[%1],16;"::"r"(dst),"l"(src))
#define CPCOMMIT() asm volatile("cp.async.commit_group;" ::: "memory")
#define CPWAIT1() asm volatile("cp.async.wait_group 1;" ::: "memory")
#define CPWAIT0() asm volatile("cp.async.wait_group 0;" ::: "memory")

// ---------- prepass: fp32 weights -> bf16 hi/lo tile planes ----------
extern "C" __global__ void __launch_bounds__(NT,1)
prep_weights(const float* __restrict__ W1,const float* __restrict__ W2,const float* __restrict__ W3){
  int t = blockIdx.x*NT + threadIdx.x;
  if(t < 8192){                            // W1: 256n x 64k
    int n=t>>5, k=(t&31)*2, kk=k&15;
    uint32_t hi,lo; split2(W1[n*64+k],W1[n*64+k+1],hi,lo);
    int off=(k>>4)*24576 + n*48 + (kk>>3)*16 + (kk&7)*2;
    *(uint32_t*)(gW1d+off)=hi; *(uint32_t*)(gW1d+off+12288)=lo;
  } else if(t < 40960){                    // W2: 256n x 256k
    int t2=t-8192, n=t2>>7, k=(t2&127)*2, kk=k&15;
    uint32_t hi,lo; split2(W2[n*256+k],W2[n*256+k+1],hi,lo);
    int off=(k>>4)*24576 + n*48 + (kk>>3)*16 + (kk&7)*2;
    *(uint32_t*)(gW2d+off)=hi; *(uint32_t*)(gW2d+off+12288)=lo;
  } else if(t < 49152){                    // W3: 64n x 256k
    int t3=t-40960, n=t3>>7, k=(t3&127)*2, kk=k&15;
    uint32_t hi,lo; split2(W3[n*256+k],W3[n*256+k+1],hi,lo);
    int off=(k>>4)*6144 + n*48 + (kk>>3)*16 + (kk&7)*2;
    *(uint32_t*)(gW3d+off)=hi; *(uint32_t*)(gW3d+off+3072)=lo;
  }
}

template<int CHB>
__device__ __forceinline__ void pf(uint32_t wb,int buf,const unsigned char* g,int c,int tid){
  const unsigned char* src = g + (size_t)c*CHB;
  uint32_t dst = wb + buf*WBUF;
  constexpr int TOT = CHB/16;
  #pragma unroll
  for(int i=0;i<(TOT+NT-1)/NT;++i){
    int e=tid+i*NT;
    if(TOT%NT==0 || e<TOT) CP16(dst+e*16, src+(size_t)e*16);
  }
  CPCOMMIT();
}

// k16 sweep: 2 M-tiles x NTILES n-tiles. B-hi frag feeds up to 4 mma.
template<int NTILES,bool ALO>
__device__ __forceinline__ void sweep2(float (*acc)[4],uint32_t wbase,uint32_t loofs,
                                       uint32_t a0,uint32_t a1,int nbase,int ll){
  uint32_t ah0[4],ah1[4],al0[4],al1[4];
  ldsm_x4(ah0,a0); ldsm_x4(ah1,a1);
  if(ALO){ ldsm_x4(al0,a0+512); ldsm_x4(al1,a1+512); }
  #pragma unroll
  for(int nt=0;nt<NTILES;++nt){
    uint32_t bh[2],bl[2];
    uint32_t ba = wbase + (uint32_t)((nbase+nt*8+(ll&7))*48 + ((ll>>3)&1)*16);
    ldsm_x2(bh,ba);
    mma_bf16(acc[nt],ah0,bh);
    mma_bf16(acc[NTILES+nt],ah1,bh);
    if(ALO){ mma_bf16(acc[nt],al0,bh); mma_bf16(acc[NTILES+nt],al1,bh); }
    ldsm_x2(bl,ba+loofs);
    mma_bf16(acc[nt],ah0,bl);
    mma_bf16(acc[NTILES+nt],ah1,bl);
  }
}

// LN+ReLU, cross-warp (2 N-halves) row reduction via smem partials.
__device__ __forceinline__ void ln_store2(char* sm,float (*acc)[4],int wm,int wn,int l,int pofs){
  const float* bb=(const float*)(sm+OFF_P)+pofs;
  const float* gg=bb+256; const float* be=bb+512;
  const int g=l>>2,t=l&3,m0=wm*32;
  float2* sR=(float2*)(sm+OFF_R);
  float sA[2],qA[2],sB[2],qB[2];
  #pragma unroll
  for(int mt=0;mt<2;++mt){
    float sa=0,qa=0,sb2=0,qb2=0;
    #pragma unroll
    for(int nt=0;nt<16;++nt){
      int c0=wn*128+nt*8+2*t;
      float b0=bb[c0],b1=bb[c0+1];
      float* d=acc[mt*16+nt];
      d[0]+=b0; d[1]+=b1; d[2]+=b0; d[3]+=b1;
      sa+=d[0]+d[1]; qa+=d[0]*d[0]+d[1]*d[1];
      sb2+=d[2]+d[3]; qb2+=d[2]*d[2]+d[3]*d[3];
    }
    #pragma unroll
    for(int o=1;o<=2;o<<=1){
      sa+=__shfl_xor_sync(~0u,sa,o); qa+=__shfl_xor_sync(~0u,qa,o);
      sb2+=__shfl_xor_sync(~0u,sb2,o); qb2+=__shfl_xor_sync(~0u,qb2,o);
    }
    sA[mt]=sa; qA[mt]=qa; sB[mt]=sb2; qB[mt]=qb2;
  }
  if(t==0){
    #pragma unroll
    for(int mt=0;mt<2;++mt){
      sR[(m0+mt*16+g)*2+wn]  =make_float2(sA[mt],qA[mt]);
      sR[(m0+mt*16+8+g)*2+wn]=make_float2(sB[mt],qB[mt]);
    }
  }
  __syncthreads();
  #pragma unroll
  for(int mt=0;mt<2;++mt){
    int rA=m0+mt*16+g, rB=rA+8;
    float2 pa0=sR[rA*2],pa1=sR[rA*2+1],pb0=sR[rB*2],pb1=sR[rB*2+1];
    float muA=(pa0.x+pa1.x)*(1.f/256.f);
    float rsA=rsqrtf(fmaxf((pa0.y+pa1.y)*(1.f/256.f)-muA*muA,0.f)+1e-5f);
    float muB=(pb0.x+pb1.x)*(1.f/256.f);
    float rsB=rsqrtf(fmaxf((pb0.y+pb1.y)*(1.f/256.f)-muB*muB,0.f)+1e-5f);
    #pragma unroll
    for(int nt=0;nt<16;++nt){
      int c0=wn*128+nt*8+2*t;
      float* d=acc[mt*16+nt];
      float h0=fmaxf(0.f,(d[0]-muA)*rsA*gg[c0]+be[c0]);
      float h1=fmaxf(0.f,(d[1]-muA)*rsA*gg[c0+1]+be[c0+1]);
      uint32_t hi,lo; split2(h0,h1,hi,lo);
      *(uint32_t*)(sm+OFF_H+rA*1040+c0*2)=hi;
      *(uint32_t*)(sm+OFF_H+rA*1040+512+c0*2)=lo;
      h0=fmaxf(0.f,(d[2]-muB)*rsB*gg[c0]+be[c0]);
      h1=fmaxf(0.f,(d[3]-muB)*rsB*gg[c0+1]+be[c0+1]);
      split2(h0,h1,hi,lo);
      *(uint32_t*)(sm+OFF_H+rB*1040+c0*2)=hi;
      *(uint32_t*)(sm+OFF_H+rB*1040+512+c0*2)=lo;
    }
  }
}

extern "C" __global__ void __launch_bounds__(NT,1)
shiftdec_mma(const float* __restrict__ a_bits,const float* __restrict__ shift_bits,
  const float* __restrict__ b1,const float* __restrict__ g1,const float* __restrict__ be1,
  const float* __restrict__ b2,const float* __restrict__ g2,const float* __restrict__ be2,
  const float* __restrict__ b3,float* __restrict__ out)
{
  extern __shared__ char sm[];
  const uint32_t sb=smem_u32(sm);
  const uint32_t wb=sb+OFF_WB;
  float* sPar=(float*)(sm+OFF_P);
  const int tid=threadIdx.x, w=tid>>5, l=tid&31, ll=l&15;
  const int wm=w&3, wn=w>>2, r0=blockIdx.x*128;

  pf<24576>(wb,0,gW1d,0,tid);
  pf<24576>(wb,1,gW1d,1,tid);

  sPar[tid]=b1[tid]; sPar[256+tid]=g1[tid]; sPar[512+tid]=be1[tid];
  sPar[768+tid]=b2[tid]; sPar[1024+tid]=g2[tid]; sPar[1280+tid]=be2[tid];
  if(tid<64) sPar[1536+tid]=b3[tid];

  { // stage X and a_bits as bf16 tiles (144B rows)
    const float4* xs=(const float4*)(shift_bits+(size_t)r0*64);
    const float4* as=(const float4*)(a_bits+(size_t)r0*64);
    #pragma unroll
    for(int it=0;it<8;++it){
      int e=tid+it*NT, row=e>>4, f4=e&15;
      float4 v=xs[e];
      __nv_bfloat162 p0=__floats2bfloat162_rn(v.x,v.y),p1=__floats2bfloat162_rn(v.z,v.w);
      *(uint2*)(sm+OFF_X+row*144+f4*8)=make_uint2(*(uint32_t*)&p0,*(uint32_t*)&p1);
      v=as[e];
      p0=__floats2bfloat162_rn(v.x,v.y); p1=__floats2bfloat162_rn(v.z,v.w);
      *(uint2*)(sm+OFF_A+row*144+f4*8)=make_uint2(*(uint32_t*)&p0,*(uint32_t*)&p1);
    }
  }

  float acc[32][4];
  #pragma unroll
  for(int i=0;i<32;++i){acc[i][0]=acc[i][1]=acc[i][2]=acc[i][3]=0.f;}

  // ---- GEMM1: X @ W1^T, 4 k16 chunks, 2 terms ----
  #pragma unroll 1
  for(int c=0;c<4;++c){
    if(c<3) CPWAIT1(); else CPWAIT0();
    __syncthreads();
    uint32_t a0=sb+OFF_X+(uint32_t)((wm*32+ll)*144+c*32)+(uint32_t)(l&16);
    sweep2<16,false>(acc,wb+(c&1)*WBUF,12288,a0,a0+16*144,wn*128,ll);
    __syncthreads();
    if(c+2<4) pf<24576>(wb,c&1,gW1d,c+2,tid);
  }
  pf<24576>(wb,0,gW2d,0,tid);
  pf<24576>(wb,1,gW2d,1,tid);
  ln_store2(sm,acc,wm,wn,l,0);

  #pragma unroll
  for(int i=0;i<32;++i){acc[i][0]=acc[i][1]=acc[i][2]=acc[i][3]=0.f;}

  // ---- GEMM2: h1 @ W2^T, 16 k16 chunks, 3 terms ----
  #pragma unroll 1
  for(int c=0;c<16;++c){
    if(c<15) CPWAIT1(); else CPWAIT0();
    __syncthreads();
    uint32_t a0=sb+OFF_H+(uint32_t)((wm*32+ll)*1040+c*32)+(uint32_t)(l&16);
    sweep2<16,true>(acc,wb+(c&1)*WBUF,12288,a0,a0+16*1040,wn*128,ll);
    __syncthreads();
    if(c+2<16) pf<24576>(wb,c&1,gW2d,c+2,tid);
  }
  pf<6144>(wb,0,gW3d,0,tid);
  pf<6144>(wb,1,gW3d,1,tid);
  ln_store2(sm,acc,wm,wn,l,768);

  #pragma unroll
  for(int i=0;i<8;++i){acc[i][0]=acc[i][1]=acc[i][2]=acc[i][3]=0.f;}

  // ---- GEMM3: h2 @ W3^T, 16 k16 chunks, 3 terms, N=64 (32 per warp-col) ----
  #pragma unroll 1
  for(int c=0;c<16;++c){
    if(c<15) CPWAIT1(); else CPWAIT0();
    __syncthreads();
    uint32_t a0=sb+OFF_H+(uint32_t)((wm*32+ll)*1040+c*32)+(uint32_t)(l&16);
    sweep2<4,true>(acc,wb+(c&1)*WBUF,3072,a0,a0+16*1040,wn*32,ll);
    __syncthreads();
    if(c+2<16) pf<6144>(wb,c&1,gW3d,c+2,tid);
  }

  // ---- logits(+bias) -> sP transposed [c][row] (stride 129) ----
  {
    const int g=l>>2,t=l&3,m0=wm*32;
    float* sP=(float*)(sm+OFF_PB);
    #pragma unroll
    for(int mt=0;mt<2;++mt){
      int rA=m0+mt*16+g, rB=rA+8;
      #pragma unroll
      for(int nt=0;nt<4;++nt){
        int c0=wn*32+nt*8+2*t;
        float* d=acc[mt*4+nt];
        sP[c0*129+rA]    =d[0]+sPar[1536+c0];
        sP[(c0+1)*129+rA]=d[1]+sPar[1537+c0];
        sP[c0*129+rB]    =d[2]+sPar[1536+c0];
        sP[(c0+1)*129+rB]=d[3]+sPar[1537+c0];
      }
    }
  }
  __syncthreads();

  // ---- softmax per row (warps 0-3, thread = row) ----
  if(w<4){
    int row=w*32+l;
    float* sP=(float*)(sm+OFF_PB);
    float p[64], m=-1e30f;
    #pragma unroll
    for(int c=0;c<64;++c){ p[c]=sP[c*129+row]; m=fmaxf(m,p[c]); }
    float s=0.f;
    #pragma unroll
    for(int c=0;c<64;++c){ p[c]=__expf(p[c]-m); s+=p[c]; }
    float inv=1.f/s;
    #pragma unroll
    for(int c=0;c<64;++c) sP[c*129+row]=p[c]*inv;
  }
  __syncthreads();

  // ---- causal shift-sum ----
  {
    const int q=w>>2, row=(w&3)*32+l;
    float areg[64];
    #pragma unroll
    for(int u=0;u<8;++u){
      uint4 v=*(const uint4*)(sm+OFF_A+row*144+u*16);
      __nv_bfloat162 q0=*(__nv_bfloat162*)&v.x,q1=*(__nv_bfloat162*)&v.y;
      __nv_bfloat162 q2=*(__nv_bfloat162*)&v.z,q3=*(__nv_bfloat162*)&v.w;
      areg[8*u+0]=__bfloat162float(q0.x); areg[8*u+1]=__bfloat162float(q0.y);
      areg[8*u+2]=__bfloat162float(q1.x); areg[8*u+3]=__bfloat162float(q1.y);
      areg[8*u+4]=__bfloat162float(q2.x); areg[8*u+5]=__bfloat162float(q2.y);
      areg[8*u+6]=__bfloat162float(q3.x); areg[8*u+7]=__bfloat162float(q3.y);
    }
    float o[32];
    #pragma unroll
    for(int j=0;j<32;++j)o[j]=0.f;
    const float* sP=(const float*)(sm+OFF_PB);
    if(q==0){
      #pragma unroll
      for(int s=0;s<32;++s){
        float pv=sP[s*129+row];
        #pragma unroll
        for(int j=0;j<32;++j) if(j>=s) o[j]+=pv*areg[j-s];
      }
    } else {
      #pragma unroll
      for(int s=0;s<64;++s){
        float pv=sP[s*129+row];
        #pragma unroll
        for(int j=0;j<32;++j) if(32+j-s>=0) o[j]+=pv*areg[32+j-s];
      }
    }
    float* op=out+(size_t)(r0+row)*64+q*32;
    #pragma unroll
    for(int c4=0;c4<8;++c4)
      *(float4*)(op+c4*4)=make_float4(o[4*c4],o[4*c4+1],o[4*c4+2],o[4*c4+3]);
  }
}

extern "C" void kernel_launch(void* const* d_in, const int* in_sizes, int n_in,
                              void* d_out, int out_size)
{
  const float* a_bits     = (const float*)d_in[0];
  const float* shift_bits = (const float*)d_in[1];
  const float* W1  = (const float*)d_in[2];
  const float* b1  = (const float*)d_in[3];
  const float* g1  = (const float*)d_in[4];
  const float* be1 = (const float*)d_in[5];
  const float* W2  = (const float*)d_in[6];
  const float* b2  = (const float*)d_in[7];
  const float* g2  = (const float*)d_in[8];
  const float* be2 = (const float*)d_in[9];
  const float* W3  = (const float*)d_in[10];
  const float* b3  = (const float*)d_in[11];
  float* out = (float*)d_out;

  const int B = in_sizes[0] / 64;      // 32768
  const int grid = B / 128;            // 256

  prep_weights<<<192, NT>>>(W1, W2, W3);

  cudaFuncSetAttribute(shiftdec_mma,
                       cudaFuncAttributeMaxDynamicSharedMemorySize, SMEM_TOTAL);
  shiftdec_mma<<<grid, NT, SMEM_TOTAL>>>(a_bits, shift_bits,
                                         b1, g1, be1,
                                         b2, g2, be2,
                                         b3, out);
}